// round 7
// baseline (speedup 1.0000x reference)
#include <cuda_runtime.h>
#include <cuda_fp16.h>

#define NUc 100000
#define NIc 50000
#define NVc 150000   // NUc + NIc
#define Dc  64
#define NEc 1000000

// ---------------- scratch ------------------------------------------------
__device__ float g_all[(size_t)NVc * Dc];   // current embeddings (fp32)
__device__ float g_acc[(size_t)NVc * Dc];   // running sum for final mean
__device__ uint2 g_X1h[(size_t)NVc * 16];   // X * D^-1/2, fp16 (64 halves/row)
__device__ uint2 g_Eh [(size_t)NVc * 16];   // hyperedge embs * De^-1, fp16
__device__ int   g_deg[NVc];
__device__ float g_isq[NVc];                // deg^-1/2 (0 if deg==0)
__device__ float g_inv[NVc];                // deg^-1   (0 if deg==0)
__device__ int   g_off[NVc];                // CSR row offsets
__device__ int   g_cur[NVc];                // fill cursors
__device__ int   g_adj[NEc * 2];            // neighbor lists
__device__ int   g_bsum[256];               // scan partials

// ---------------- degree / normalization --------------------------------

__global__ void k_zero_deg() {
    int i = blockIdx.x * blockDim.x + threadIdx.x;
    if (i < NVc) g_deg[i] = 0;
}

__global__ void k_count(const int* __restrict__ eu, const int* __restrict__ ei) {
    int e = blockIdx.x * blockDim.x + threadIdx.x;
    if (e < NEc) {
        atomicAdd(&g_deg[eu[e]], 1);
        atomicAdd(&g_deg[NUc + ei[e]], 1);
    }
}

__global__ void k_norm() {
    int n = blockIdx.x * blockDim.x + threadIdx.x;
    if (n < NVc) {
        int d = g_deg[n];
        if (d > 0) {
            float fd = (float)d;
            g_isq[n] = rsqrtf(fd);
            g_inv[n] = 1.0f / fd;
        } else {
            g_isq[n] = 0.0f;
            g_inv[n] = 0.0f;
        }
    }
}

// ---------------- exclusive scan of g_deg -> g_off -----------------------

__global__ void k_scan1() {
    __shared__ int s[1024];
    int i = blockIdx.x * 1024 + threadIdx.x;
    int v = (i < NVc) ? g_deg[i] : 0;
    s[threadIdx.x] = v;
    __syncthreads();
    #pragma unroll
    for (int d = 1; d < 1024; d <<= 1) {
        int t = (threadIdx.x >= d) ? s[threadIdx.x - d] : 0;
        __syncthreads();
        s[threadIdx.x] += t;
        __syncthreads();
    }
    if (i < NVc) g_off[i] = s[threadIdx.x] - v;
    if (threadIdx.x == 1023) g_bsum[blockIdx.x] = s[1023];
}

__global__ void k_scan2(int nblocks) {
    __shared__ int s[256];
    int v = (threadIdx.x < nblocks) ? g_bsum[threadIdx.x] : 0;
    s[threadIdx.x] = v;
    __syncthreads();
    #pragma unroll
    for (int d = 1; d < 256; d <<= 1) {
        int t = (threadIdx.x >= d) ? s[threadIdx.x - d] : 0;
        __syncthreads();
        s[threadIdx.x] += t;
        __syncthreads();
    }
    g_bsum[threadIdx.x] = s[threadIdx.x] - v;
}

__global__ void k_scan3() {
    int i = blockIdx.x * blockDim.x + threadIdx.x;
    if (i < NVc) {
        int o = g_off[i] + g_bsum[i >> 10];
        g_off[i] = o;
        g_cur[i] = o;
    }
}

__global__ void k_fill(const int* __restrict__ eu, const int* __restrict__ ei) {
    int e = blockIdx.x * blockDim.x + threadIdx.x;
    if (e < NEc) {
        int u = eu[e];
        int it = NUc + ei[e];
        int pu = atomicAdd(&g_cur[u], 1);
        g_adj[pu] = it;
        int pi = atomicAdd(&g_cur[it], 1);
        g_adj[pi] = u;
    }
}

// ---------------- embedding init -----------------------------------------
// thread handles 4 columns (one float4 / one uint2 of halves)

__global__ void k_init(const float4* __restrict__ u4, const float4* __restrict__ i4) {
    int idx = blockIdx.x * blockDim.x + threadIdx.x;
    if (idx < NVc * 16) {
        float4 v = (idx < NUc * 16) ? u4[idx] : i4[idx - NUc * 16];
        ((float4*)g_all)[idx] = v;
        ((float4*)g_acc)[idx] = v;
        float s = g_isq[idx >> 4];
        __half2 p0 = __floats2half2_rn(v.x * s, v.y * s);
        __half2 p1 = __floats2half2_rn(v.z * s, v.w * s);
        uint2 h;
        h.x = *(unsigned*)&p0;
        h.y = *(unsigned*)&p1;
        g_X1h[idx] = h;
    }
}

// ---------------- gather 1: E'[n] = inv[n] * sum X1[opp] -----------------
// one warp per node; lane l covers cols (2l, 2l+1); fp16 rows, fp32 accum

__global__ void __launch_bounds__(256) k_gatherE() {
    int lane = threadIdx.x & 31;
    int w    = threadIdx.x >> 5;
    int n = blockIdx.x * 8 + w;
    if (n >= NVc) return;

    int deg = g_deg[n];
    const int* __restrict__ adj = g_adj + g_off[n];
    const __half2* __restrict__ X = (const __half2*)g_X1h;

    float2 acc = make_float2(0.f, 0.f);
    int j = 0;
    for (; j + 3 < deg; j += 4) {
        int o0 = adj[j], o1 = adj[j+1], o2 = adj[j+2], o3 = adj[j+3];
        float2 f0 = __half22float2(X[o0 * 32 + lane]);
        float2 f1 = __half22float2(X[o1 * 32 + lane]);
        float2 f2 = __half22float2(X[o2 * 32 + lane]);
        float2 f3 = __half22float2(X[o3 * 32 + lane]);
        acc.x += (f0.x + f1.x) + (f2.x + f3.x);
        acc.y += (f0.y + f1.y) + (f2.y + f3.y);
    }
    for (; j < deg; j++) {
        float2 f = __half22float2(X[adj[j] * 32 + lane]);
        acc.x += f.x; acc.y += f.y;
    }
    float inv = g_inv[n];
    __half2 h = __floats2half2_rn(acc.x * inv, acc.y * inv);
    ((__half2*)g_Eh)[n * 32 + lane] = h;
}

// ---------------- fused: gather2 + 2x GEMV + lrelu + L2norm --------------
// one warp per node; gather from fp16 E; shfl-broadcast GEMV

__global__ void __launch_bounds__(256) k_layer(const float* __restrict__ Wgc,
                                               const float* __restrict__ bgc,
                                               const float* __restrict__ Wbi,
                                               const float* __restrict__ bbi,
                                               float* __restrict__ out) {
    __shared__ float sWg[64 * 64];  // transposed: sWg[k*64+j] = Wgc[j*64+k]
    __shared__ float sWb[64 * 64];
    __shared__ float sbg[64], sbb[64];

    for (int idx = threadIdx.x; idx < 4096; idx += 256) {
        int k = idx >> 6, jj = idx & 63;
        sWg[idx] = Wgc[jj * 64 + k];
        sWb[idx] = Wbi[jj * 64 + k];
    }
    if (threadIdx.x < 64) {
        sbg[threadIdx.x] = bgc[threadIdx.x];
        sbb[threadIdx.x] = bbi[threadIdx.x];
    }
    __syncthreads();

    int lane = threadIdx.x & 31;
    int w    = threadIdx.x >> 5;
    int n = blockIdx.x * 8 + w;
    if (n >= NVc) return;

    // ---- gather Y[n] = sum E'[opp] ; lane covers cols (2l, 2l+1) ----
    int deg = g_deg[n];
    const int* __restrict__ adj = g_adj + g_off[n];
    const __half2* __restrict__ E = (const __half2*)g_Eh;

    float2 y = make_float2(0.f, 0.f);
    int j = 0;
    for (; j + 3 < deg; j += 4) {
        int o0 = adj[j], o1 = adj[j+1], o2 = adj[j+2], o3 = adj[j+3];
        float2 f0 = __half22float2(E[o0 * 32 + lane]);
        float2 f1 = __half22float2(E[o1 * 32 + lane]);
        float2 f2 = __half22float2(E[o2 * 32 + lane]);
        float2 f3 = __half22float2(E[o3 * 32 + lane]);
        y.x += (f0.x + f1.x) + (f2.x + f3.x);
        y.y += (f0.y + f1.y) + (f2.y + f3.y);
    }
    for (; j < deg; j++) {
        float2 f = __half22float2(E[adj[j] * 32 + lane]);
        y.x += f.x; y.y += f.y;
    }

    float isq = g_isq[n];
    // g on cols (2l, 2l+1)
    float gx = y.x * isq, gy = y.y * isq;
    float2 x2 = ((const float2*)g_all)[n * 32 + lane];
    float mx = x2.x * gx, my = x2.y * gy;

    // ---- dual GEMV: out_j = sum_k W[j][k] * v_k ; v_k on lane k>>1 ----
    float a0 = 0.f, a1 = 0.f, b0 = 0.f, b1 = 0.f;
    #pragma unroll
    for (int k = 0; k < 64; k += 2) {
        float gk0 = __shfl_sync(0xffffffffu, gx, k >> 1);
        float gk1 = __shfl_sync(0xffffffffu, gy, k >> 1);
        float mk0 = __shfl_sync(0xffffffffu, mx, k >> 1);
        float mk1 = __shfl_sync(0xffffffffu, my, k >> 1);
        a0 = fmaf(sWg[k * 64 + lane],            gk0, a0);
        a1 = fmaf(sWg[k * 64 + 32 + lane],       gk0, a1);
        b0 = fmaf(sWb[k * 64 + lane],            mk0, b0);
        b1 = fmaf(sWb[k * 64 + 32 + lane],       mk0, b1);
        a0 = fmaf(sWg[(k + 1) * 64 + lane],      gk1, a0);
        a1 = fmaf(sWg[(k + 1) * 64 + 32 + lane], gk1, a1);
        b0 = fmaf(sWb[(k + 1) * 64 + lane],      mk1, b0);
        b1 = fmaf(sWb[(k + 1) * 64 + 32 + lane], mk1, b1);
    }

    float x0 = g_all[n * 64 + lane];
    float x1 = g_all[n * 64 + 32 + lane];

    float h0 = a0 + sbg[lane]      + x0; h0 = h0 > 0.f ? h0 : 0.2f * h0;
    float h1 = a1 + sbg[lane + 32] + x1; h1 = h1 > 0.f ? h1 : 0.2f * h1;
    float p0 = b0 + sbb[lane];           p0 = p0 > 0.f ? p0 : 0.2f * p0;
    float p1 = b1 + sbb[lane + 32];      p1 = p1 > 0.f ? p1 : 0.2f * p1;

    float n0 = h0 + p0, n1 = h1 + p1;
    float s = n0 * n0 + n1 * n1;
    #pragma unroll
    for (int o = 16; o; o >>= 1) s += __shfl_xor_sync(0xffffffffu, s, o);
    float invn = 1.0f / fmaxf(sqrtf(s), 1e-12f);
    n0 *= invn; n1 *= invn;

    if (out) {
        out[n * 64 + lane]      = (g_acc[n * 64 + lane]      + n0) * 0.25f;
        out[n * 64 + 32 + lane] = (g_acc[n * 64 + 32 + lane] + n1) * 0.25f;
    } else {
        g_all[n * 64 + lane]       = n0;
        g_all[n * 64 + 32 + lane]  = n1;
        g_acc[n * 64 + lane]      += n0;
        g_acc[n * 64 + 32 + lane] += n1;
        __half* X1s = (__half*)g_X1h;
        X1s[n * 64 + lane]      = __float2half(n0 * isq);
        X1s[n * 64 + 32 + lane] = __float2half(n1 * isq);
    }
}

// ---------------- launch --------------------------------------------------

extern "C" void kernel_launch(void* const* d_in, const int* in_sizes, int n_in,
                              void* d_out, int out_size) {
    const float* u_emb = (const float*)d_in[0];
    const float* i_emb = (const float*)d_in[1];
    const float* Wgc   = (const float*)d_in[2];
    const float* bgc   = (const float*)d_in[3];
    const float* Wbi   = (const float*)d_in[4];
    const float* bbi   = (const float*)d_in[5];
    const int*   eu    = (const int*)d_in[6];
    const int*   ei    = (const int*)d_in[7];
    float* out = (float*)d_out;

    const int nodeVecBlocks  = (NVc * 16 + 255) / 256;   // 9375
    const int nodeBlocks     = (NVc + 255) / 256;        // 586
    const int edgeBlocks     = (NEc + 255) / 256;        // 3907
    const int scanBlocks     = (NVc + 1023) / 1024;      // 147
    const int warpNodeBlocks = (NVc + 7) / 8;            // 18750

    k_zero_deg<<<nodeBlocks, 256>>>();
    k_count<<<edgeBlocks, 256>>>(eu, ei);
    k_norm<<<nodeBlocks, 256>>>();
    k_scan1<<<scanBlocks, 1024>>>();
    k_scan2<<<1, 256>>>(scanBlocks);
    k_scan3<<<nodeBlocks, 256>>>();
    k_fill<<<edgeBlocks, 256>>>(eu, ei);
    k_init<<<nodeVecBlocks, 256>>>((const float4*)u_emb, (const float4*)i_emb);

    for (int l = 0; l < 3; l++) {
        k_gatherE<<<warpNodeBlocks, 256>>>();
        k_layer<<<warpNodeBlocks, 256>>>(Wgc + l * 4096, bgc + l * 64,
                                         Wbi + l * 4096, bbi + l * 64,
                                         (l == 2) ? out : (float*)0);
    }
}

// round 8
// speedup vs baseline: 2.9091x; 2.9091x over previous
#include <cuda_runtime.h>
#include <cuda_fp16.h>

#define NUc 100000
#define NIc 50000
#define NVc 150000   // NUc + NIc
#define Dc  64
#define NEc 1000000

// ---------------- scratch ------------------------------------------------
__device__ float g_all[(size_t)NVc * Dc];   // current embeddings (fp32)
__device__ float g_acc[(size_t)NVc * Dc];   // running sum for final mean
__device__ uint2 g_X1h[(size_t)NVc * 16];   // X * D^-1/2, fp16 (64 halves/row)
__device__ uint2 g_Eh [(size_t)NVc * 16];   // hyperedge embs * De^-1, fp16
__device__ int   g_deg[NVc];
__device__ float g_isq[NVc];                // deg^-1/2 (0 if deg==0)
__device__ float g_inv[NVc];                // deg^-1   (0 if deg==0)
__device__ int   g_off[NVc];                // CSR row offsets
__device__ int   g_cur[NVc];                // fill cursors
__device__ int   g_adj[NEc * 2];            // neighbor lists
__device__ int   g_bsum[256];               // scan partials

// ---------------- degree / normalization --------------------------------

__global__ void k_zero_deg() {
    int i = blockIdx.x * blockDim.x + threadIdx.x;
    if (i < NVc) g_deg[i] = 0;
}

__global__ void k_count(const int* __restrict__ eu, const int* __restrict__ ei) {
    int e = blockIdx.x * blockDim.x + threadIdx.x;
    if (e < NEc) {
        atomicAdd(&g_deg[eu[e]], 1);
        atomicAdd(&g_deg[NUc + ei[e]], 1);
    }
}

__global__ void k_norm() {
    int n = blockIdx.x * blockDim.x + threadIdx.x;
    if (n < NVc) {
        int d = g_deg[n];
        if (d > 0) {
            float fd = (float)d;
            g_isq[n] = rsqrtf(fd);
            g_inv[n] = 1.0f / fd;
        } else {
            g_isq[n] = 0.0f;
            g_inv[n] = 0.0f;
        }
    }
}

// ---------------- exclusive scan of g_deg -> g_off -----------------------

__global__ void k_scan1() {
    __shared__ int s[1024];
    int i = blockIdx.x * 1024 + threadIdx.x;
    int v = (i < NVc) ? g_deg[i] : 0;
    s[threadIdx.x] = v;
    __syncthreads();
    #pragma unroll
    for (int d = 1; d < 1024; d <<= 1) {
        int t = (threadIdx.x >= d) ? s[threadIdx.x - d] : 0;
        __syncthreads();
        s[threadIdx.x] += t;
        __syncthreads();
    }
    if (i < NVc) g_off[i] = s[threadIdx.x] - v;
    if (threadIdx.x == 1023) g_bsum[blockIdx.x] = s[1023];
}

__global__ void k_scan2(int nblocks) {
    __shared__ int s[256];
    int v = (threadIdx.x < nblocks) ? g_bsum[threadIdx.x] : 0;
    s[threadIdx.x] = v;
    __syncthreads();
    #pragma unroll
    for (int d = 1; d < 256; d <<= 1) {
        int t = (threadIdx.x >= d) ? s[threadIdx.x - d] : 0;
        __syncthreads();
        s[threadIdx.x] += t;
        __syncthreads();
    }
    g_bsum[threadIdx.x] = s[threadIdx.x] - v;
}

__global__ void k_scan3() {
    int i = blockIdx.x * blockDim.x + threadIdx.x;
    if (i < NVc) {
        int o = g_off[i] + g_bsum[i >> 10];
        g_off[i] = o;
        g_cur[i] = o;
    }
}

__global__ void k_fill(const int* __restrict__ eu, const int* __restrict__ ei) {
    int e = blockIdx.x * blockDim.x + threadIdx.x;
    if (e < NEc) {
        int u = eu[e];
        int it = NUc + ei[e];
        int pu = atomicAdd(&g_cur[u], 1);
        g_adj[pu] = it;
        int pi = atomicAdd(&g_cur[it], 1);
        g_adj[pi] = u;
    }
}

// ---------------- embedding init -----------------------------------------

__global__ void k_init(const float4* __restrict__ u4, const float4* __restrict__ i4) {
    int idx = blockIdx.x * blockDim.x + threadIdx.x;
    if (idx < NVc * 16) {
        float4 v = (idx < NUc * 16) ? u4[idx] : i4[idx - NUc * 16];
        ((float4*)g_all)[idx] = v;
        ((float4*)g_acc)[idx] = v;
        float s = g_isq[idx >> 4];
        __half2 p0 = __floats2half2_rn(v.x * s, v.y * s);
        __half2 p1 = __floats2half2_rn(v.z * s, v.w * s);
        uint2 h;
        h.x = *(unsigned*)&p0;
        h.y = *(unsigned*)&p1;
        g_X1h[idx] = h;
    }
}

// ---------------- gather 1: E'[n] = inv[n] * sum X1[opp] -----------------
// one warp per node; lane l covers cols (2l, 2l+1); fp16 rows, fp32 accum

__global__ void __launch_bounds__(256) k_gatherE() {
    int lane = threadIdx.x & 31;
    int w    = threadIdx.x >> 5;
    int n = blockIdx.x * 8 + w;
    if (n >= NVc) return;

    int deg = g_deg[n];
    const int* __restrict__ adj = g_adj + g_off[n];
    const __half2* __restrict__ X = (const __half2*)g_X1h;

    float2 acc = make_float2(0.f, 0.f);
    int j = 0;
    for (; j + 3 < deg; j += 4) {
        int o0 = adj[j], o1 = adj[j+1], o2 = adj[j+2], o3 = adj[j+3];
        float2 f0 = __half22float2(X[o0 * 32 + lane]);
        float2 f1 = __half22float2(X[o1 * 32 + lane]);
        float2 f2 = __half22float2(X[o2 * 32 + lane]);
        float2 f3 = __half22float2(X[o3 * 32 + lane]);
        acc.x += (f0.x + f1.x) + (f2.x + f3.x);
        acc.y += (f0.y + f1.y) + (f2.y + f3.y);
    }
    for (; j < deg; j++) {
        float2 f = __half22float2(X[adj[j] * 32 + lane]);
        acc.x += f.x; acc.y += f.y;
    }
    float inv = g_inv[n];
    __half2 h = __floats2half2_rn(acc.x * inv, acc.y * inv);
    ((__half2*)g_Eh)[n * 32 + lane] = h;
}

// ---------------- fused: gather2 + 2x GEMV + lrelu + L2norm --------------
// PERSISTENT grid (888 blocks); one warp per node per iteration.
// Weights staged once per block: coalesced global read, padded transposed smem.

#define WPITCH 65

__global__ void __launch_bounds__(256) k_layer(const float* __restrict__ Wgc,
                                               const float* __restrict__ bgc,
                                               const float* __restrict__ Wbi,
                                               const float* __restrict__ bbi,
                                               float* __restrict__ out) {
    __shared__ float sWg[64 * WPITCH];  // sWg[k*WPITCH+j] = Wgc[j][k]
    __shared__ float sWb[64 * WPITCH];
    __shared__ float sbg[64], sbb[64];

    for (int idx = threadIdx.x; idx < 4096; idx += 256) {
        int j = idx >> 6, k = idx & 63;        // coalesced read: consecutive k
        sWg[k * WPITCH + j] = Wgc[idx];
        sWb[k * WPITCH + j] = Wbi[idx];
    }
    if (threadIdx.x < 64) {
        sbg[threadIdx.x] = bgc[threadIdx.x];
        sbb[threadIdx.x] = bbi[threadIdx.x];
    }
    __syncthreads();

    int lane = threadIdx.x & 31;
    int w    = threadIdx.x >> 5;

    for (int n = blockIdx.x * 8 + w; n < NVc; n += gridDim.x * 8) {
        // ---- gather Y[n] = sum E'[opp] ; lane covers cols (2l, 2l+1) ----
        int deg = g_deg[n];
        const int* __restrict__ adj = g_adj + g_off[n];
        const __half2* __restrict__ E = (const __half2*)g_Eh;

        float2 y = make_float2(0.f, 0.f);
        int j = 0;
        for (; j + 3 < deg; j += 4) {
            int o0 = adj[j], o1 = adj[j+1], o2 = adj[j+2], o3 = adj[j+3];
            float2 f0 = __half22float2(E[o0 * 32 + lane]);
            float2 f1 = __half22float2(E[o1 * 32 + lane]);
            float2 f2 = __half22float2(E[o2 * 32 + lane]);
            float2 f3 = __half22float2(E[o3 * 32 + lane]);
            y.x += (f0.x + f1.x) + (f2.x + f3.x);
            y.y += (f0.y + f1.y) + (f2.y + f3.y);
        }
        for (; j < deg; j++) {
            float2 f = __half22float2(E[adj[j] * 32 + lane]);
            y.x += f.x; y.y += f.y;
        }

        float isq = g_isq[n];
        float gx = y.x * isq, gy = y.y * isq;      // g on cols (2l, 2l+1)
        float2 x2 = ((const float2*)g_all)[n * 32 + lane];
        float mx = x2.x * gx, my = x2.y * gy;

        // ---- dual GEMV: out_j = sum_k W[j][k] * v_k ----
        float a0 = 0.f, a1 = 0.f, b0 = 0.f, b1 = 0.f;
        #pragma unroll
        for (int k = 0; k < 64; k += 2) {
            float gk0 = __shfl_sync(0xffffffffu, gx, k >> 1);
            float gk1 = __shfl_sync(0xffffffffu, gy, k >> 1);
            float mk0 = __shfl_sync(0xffffffffu, mx, k >> 1);
            float mk1 = __shfl_sync(0xffffffffu, my, k >> 1);
            a0 = fmaf(sWg[k * WPITCH + lane],            gk0, a0);
            a1 = fmaf(sWg[k * WPITCH + 32 + lane],       gk0, a1);
            b0 = fmaf(sWb[k * WPITCH + lane],            mk0, b0);
            b1 = fmaf(sWb[k * WPITCH + 32 + lane],       mk0, b1);
            a0 = fmaf(sWg[(k + 1) * WPITCH + lane],      gk1, a0);
            a1 = fmaf(sWg[(k + 1) * WPITCH + 32 + lane], gk1, a1);
            b0 = fmaf(sWb[(k + 1) * WPITCH + lane],      mk1, b0);
            b1 = fmaf(sWb[(k + 1) * WPITCH + 32 + lane], mk1, b1);
        }

        float x0 = g_all[n * 64 + lane];
        float x1 = g_all[n * 64 + 32 + lane];

        float h0 = a0 + sbg[lane]      + x0; h0 = h0 > 0.f ? h0 : 0.2f * h0;
        float h1 = a1 + sbg[lane + 32] + x1; h1 = h1 > 0.f ? h1 : 0.2f * h1;
        float p0 = b0 + sbb[lane];           p0 = p0 > 0.f ? p0 : 0.2f * p0;
        float p1 = b1 + sbb[lane + 32];      p1 = p1 > 0.f ? p1 : 0.2f * p1;

        float n0 = h0 + p0, n1 = h1 + p1;
        float s = n0 * n0 + n1 * n1;
        #pragma unroll
        for (int o = 16; o; o >>= 1) s += __shfl_xor_sync(0xffffffffu, s, o);
        float invn = 1.0f / fmaxf(sqrtf(s), 1e-12f);
        n0 *= invn; n1 *= invn;

        if (out) {
            out[n * 64 + lane]      = (g_acc[n * 64 + lane]      + n0) * 0.25f;
            out[n * 64 + 32 + lane] = (g_acc[n * 64 + 32 + lane] + n1) * 0.25f;
        } else {
            g_all[n * 64 + lane]       = n0;
            g_all[n * 64 + 32 + lane]  = n1;
            g_acc[n * 64 + lane]      += n0;
            g_acc[n * 64 + 32 + lane] += n1;
            __half* X1s = (__half*)g_X1h;
            X1s[n * 64 + lane]      = __float2half(n0 * isq);
            X1s[n * 64 + 32 + lane] = __float2half(n1 * isq);
        }
    }
}

// ---------------- launch --------------------------------------------------

extern "C" void kernel_launch(void* const* d_in, const int* in_sizes, int n_in,
                              void* d_out, int out_size) {
    const float* u_emb = (const float*)d_in[0];
    const float* i_emb = (const float*)d_in[1];
    const float* Wgc   = (const float*)d_in[2];
    const float* bgc   = (const float*)d_in[3];
    const float* Wbi   = (const float*)d_in[4];
    const float* bbi   = (const float*)d_in[5];
    const int*   eu    = (const int*)d_in[6];
    const int*   ei    = (const int*)d_in[7];
    float* out = (float*)d_out;

    const int nodeVecBlocks  = (NVc * 16 + 255) / 256;   // 9375
    const int nodeBlocks     = (NVc + 255) / 256;        // 586
    const int edgeBlocks     = (NEc + 255) / 256;        // 3907
    const int scanBlocks     = (NVc + 1023) / 1024;      // 147
    const int warpNodeBlocks = (NVc + 7) / 8;            // 18750
    const int layerBlocks    = 888;                      // 148 SMs x 6

    k_zero_deg<<<nodeBlocks, 256>>>();
    k_count<<<edgeBlocks, 256>>>(eu, ei);
    k_norm<<<nodeBlocks, 256>>>();
    k_scan1<<<scanBlocks, 1024>>>();
    k_scan2<<<1, 256>>>(scanBlocks);
    k_scan3<<<nodeBlocks, 256>>>();
    k_fill<<<edgeBlocks, 256>>>(eu, ei);
    k_init<<<nodeVecBlocks, 256>>>((const float4*)u_emb, (const float4*)i_emb);

    for (int l = 0; l < 3; l++) {
        k_gatherE<<<warpNodeBlocks, 256>>>();
        k_layer<<<layerBlocks, 256>>>(Wgc + l * 4096, bgc + l * 64,
                                      Wbi + l * 4096, bbi + l * 64,
                                      (l == 2) ? out : (float*)0);
    }
}